// round 1
// baseline (speedup 1.0000x reference)
#include <cuda_runtime.h>
#include <math.h>

// ---------------- problem constants ----------------
// B=2, T=5, H=W=64, C=192, HEADS=6, HD=32, window 8x8 shift 4,4
// L = 20480, ROWS = B*L = 40960
// windows per batch nW = 64, B_ = 128, N = T*64 = 320
#define ROWS      40960
#define CDIM      192
#define NWIN      320          // tokens per window
#define BH        768          // B_ * HEADS
#define MLPH      768
#define QK_SCALE  0.17677669529663687f   // 32^-0.5

// ---------------- scratch (device globals; no allocation allowed) ----------------
__device__ float g_h [ (size_t)ROWS * CDIM ];        // LN output
__device__ float g_q [ (size_t)BH * NWIN * 32 ];     // (b_*6+h, n, d)
__device__ float g_k [ (size_t)BH * NWIN * 32 ];
__device__ float g_v [ (size_t)BH * NWIN * 32 ];
__device__ float g_a [ (size_t)ROWS * CDIM ];        // attn out, window rows
__device__ float g_x1[ (size_t)ROWS * CDIM ];        // after attn residual
__device__ float g_g [ (size_t)ROWS * MLPH ];        // gelu(fc1)
__device__ float g_bias6[ 6 * NWIN * NWIN ];         // (head, n, m)

// window-row -> x-row permutation (roll -4,-4 + window partition; self-inverse use)
__device__ __forceinline__ int winmap(int wr) {
    int b_ = wr / NWIN, n = wr - b_ * NWIN;
    int b  = b_ >> 6,  w = b_ & 63;
    int wh = w >> 3,   ww = w & 7;
    int t  = n >> 6;
    int rem = n & 63;
    int i = rem >> 3, j = rem & 7;
    int hs = (wh * 8 + i + 4) & 63;
    int ws = (ww * 8 + j + 4) & 63;
    return ((b * 5 + t) << 12) + (hs << 6) + ws;   // ((b*5+t)*64+hs)*64+ws
}

// ---------------- relative-position bias precompute ----------------
__global__ void bias_kernel(const float* __restrict__ table) {
    int e = blockIdx.x * 1024 + threadIdx.x;
    if (e >= 6 * NWIN * NWIN) return;
    int head = e / (NWIN * NWIN);
    int r = e - head * (NWIN * NWIN);
    int n = r / NWIN, m = r - n * NWIN;
    int t1 = n >> 6, p1 = n & 63, i1 = p1 >> 3, j1 = p1 & 7;
    int t2 = m >> 6, p2 = m & 63, i2 = p2 >> 3, j2 = p2 & 7;
    int idx = (t1 - t2 + 7) * 15 + (i1 - i2 + 7) + (j1 - j2);
    g_bias6[e] = table[idx * 6 + head];
}

// ---------------- LayerNorm (one warp per row) ----------------
template<int SRC>   // 0: use 'in' param, 1: use g_x1
__global__ __launch_bounds__(256) void ln_kernel(const float* __restrict__ in,
                                                 const float* __restrict__ gw,
                                                 const float* __restrict__ bw) {
    int row  = blockIdx.x * 8 + (threadIdx.x >> 5);
    int lane = threadIdx.x & 31;
    const float* src = (SRC == 0) ? in : g_x1;
    const float* p = src + (size_t)row * CDIM;
    float v[6];
    float s = 0.f;
#pragma unroll
    for (int u = 0; u < 6; u++) { v[u] = p[lane + 32 * u]; s += v[u]; }
#pragma unroll
    for (int o = 16; o; o >>= 1) s += __shfl_xor_sync(0xffffffffu, s, o);
    float mu = s * (1.0f / CDIM);
    float q = 0.f;
#pragma unroll
    for (int u = 0; u < 6; u++) { float d = v[u] - mu; q += d * d; }
#pragma unroll
    for (int o = 16; o; o >>= 1) q += __shfl_xor_sync(0xffffffffu, q, o);
    float rs = rsqrtf(q * (1.0f / CDIM) + 1e-5f);
    float* o = g_h + (size_t)row * CDIM;
#pragma unroll
    for (int u = 0; u < 6; u++) {
        int c = lane + 32 * u;
        o[c] = (v[u] - mu) * rs * gw[c] + bw[c];
    }
}

// ---------------- GEMM epilogues ----------------
struct EpiQKV {
    __device__ void operator()(int wr, int oc, float val) const {
        int which = oc / CDIM;
        int rem = oc - which * CDIM;
        int h = rem >> 5, d = rem & 31;
        int b_ = wr / NWIN, n = wr - b_ * NWIN;
        size_t off = ((size_t)(b_ * 6 + h)) * (NWIN * 32) + (size_t)n * 32 + d;
        if (which == 0)      g_q[off] = val * QK_SCALE;
        else if (which == 1) g_k[off] = val;
        else                 g_v[off] = val;
    }
};
struct EpiProj {
    const float* x;
    __device__ void operator()(int wr, int c, float v) const {
        int dst = winmap(wr);
        size_t o = (size_t)dst * CDIM + c;
        g_x1[o] = x[o] + v;
    }
};
struct EpiGelu {
    __device__ void operator()(int r, int c, float v) const {
        g_g[(size_t)r * MLPH + c] = 0.5f * v * (1.0f + erff(v * 0.7071067811865476f));
    }
};
struct EpiOut {
    float* out;
    __device__ void operator()(int r, int c, float v) const {
        size_t o = (size_t)r * CDIM + c;
        out[o] = g_x1[o] + v;
    }
};

// ---------------- generic 64x64x16 SGEMM: out = A @ W^T + bias, fused epilogue ----
// ASRC: 0 = A param, 1 = g_h, 2 = g_a, 3 = g_g.  GATHER: A rows via winmap.
// grid = (N/64, M/64); M,N,K all multiples of tile sizes (guaranteed by shapes).
template<int ASRC, bool GATHER, class Epi>
__global__ __launch_bounds__(256) void gemm64(const float* __restrict__ Aparam,
                                              const float* __restrict__ W,
                                              const float* __restrict__ bias,
                                              int K, Epi epi) {
    const float* A = (ASRC == 0) ? Aparam : (ASRC == 1) ? g_h : (ASRC == 2) ? g_a : g_g;
    __shared__ float As[64][17];
    __shared__ float Bs[64][17];
    int tid  = threadIdx.x;
    int bm   = blockIdx.y, bn = blockIdx.x;
    int arow = tid >> 2;
    int kq   = (tid & 3) << 2;
    int grow = bm * 64 + arow;
    int asrc = GATHER ? winmap(grow) : grow;
    const float* Ap = A + (size_t)asrc * K + kq;
    const float* Wp = W + (size_t)(bn * 64 + arow) * K + kq;
    int tx = tid & 15, ty = tid >> 4;
    float acc[4][4] = {};
    for (int k0 = 0; k0 < K; k0 += 16) {
        float4 a4 = *(const float4*)(Ap + k0);
        float4 b4 = *(const float4*)(Wp + k0);
        As[arow][kq + 0] = a4.x; As[arow][kq + 1] = a4.y;
        As[arow][kq + 2] = a4.z; As[arow][kq + 3] = a4.w;
        Bs[arow][kq + 0] = b4.x; Bs[arow][kq + 1] = b4.y;
        Bs[arow][kq + 2] = b4.z; Bs[arow][kq + 3] = b4.w;
        __syncthreads();
#pragma unroll
        for (int kk = 0; kk < 16; kk++) {
            float av[4], bv[4];
#pragma unroll
            for (int i = 0; i < 4; i++) av[i] = As[ty * 4 + i][kk];
#pragma unroll
            for (int j = 0; j < 4; j++) bv[j] = Bs[tx * 4 + j][kk];
#pragma unroll
            for (int i = 0; i < 4; i++)
#pragma unroll
                for (int j = 0; j < 4; j++) acc[i][j] += av[i] * bv[j];
        }
        __syncthreads();
    }
#pragma unroll
    for (int i = 0; i < 4; i++)
#pragma unroll
        for (int j = 0; j < 4; j++) {
            int r = bm * 64 + ty * 4 + i;
            int c = bn * 64 + tx * 4 + j;
            epi(r, c, acc[i][j] + bias[c]);
        }
}

// ---------------- attention ----------------
// grid = (5, 768): rtile (64 q-rows), bh = b_*6 + head. 256 threads.
// smem: qs 64x33, ks 320x33, vs 320x33, Ss 64x321, lab[64]
#define ATTN_SMEM ((2112 + 10560 + 10560 + 20544) * 4 + 64 * 4)

__global__ __launch_bounds__(256) void attn_kernel() {
    extern __shared__ float sm[];
    float* qs = sm;                 // 64*33
    float* ks = qs + 2112;          // 320*33
    float* vs = ks + 10560;         // 320*33
    float* Ss = vs + 10560;         // 64*321
    int*  lab = (int*)(Ss + 20544); // 64

    int rtile = blockIdx.x;
    int bh    = blockIdx.y;
    int b_    = bh / 6;
    int head  = bh - b_ * 6;
    int tid   = threadIdx.x;

    const float* qbase = g_q + (size_t)bh * (NWIN * 32);
    const float* kbase = g_k + (size_t)bh * (NWIN * 32);
    const float* vbase = g_v + (size_t)bh * (NWIN * 32);

    for (int e = tid; e < 64 * 32; e += 256) {
        int r = e >> 5, d = e & 31;
        qs[r * 33 + d] = qbase[(size_t)(rtile * 64 + r) * 32 + d];
    }
    for (int e = tid; e < NWIN * 32; e += 256) {
        int r = e >> 5, d = e & 31;
        ks[r * 33 + d] = kbase[e];
        vs[r * 33 + d] = vbase[e];
    }
    if (tid < 64) {
        int w = b_ & 63;
        int wh = w >> 3, ww = w & 7;
        int i = tid >> 3, j = tid & 7;
        int hh = wh * 8 + i, wg = ww * 8 + j;
        int lh = hh < 56 ? 0 : (hh < 60 ? 1 : 2);
        int lw = wg < 56 ? 0 : (wg < 60 ? 1 : 2);
        lab[tid] = lh * 3 + lw;
    }
    __syncthreads();

    int tx = tid & 15, ty = tid >> 4;

    // phase 1: S = q @ k^T (q already scaled)
    float acc[4][20];
#pragma unroll
    for (int i = 0; i < 4; i++)
#pragma unroll
        for (int u = 0; u < 20; u++) acc[i][u] = 0.f;

    for (int d = 0; d < 32; d++) {
        float qv[4];
#pragma unroll
        for (int i = 0; i < 4; i++) qv[i] = qs[(ty * 4 + i) * 33 + d];
#pragma unroll
        for (int u = 0; u < 20; u++) {
            float kv = ks[(tx + 16 * u) * 33 + d];
#pragma unroll
            for (int i = 0; i < 4; i++) acc[i][u] += qv[i] * kv;
        }
    }

    // bias + shift mask, store S
    const float* bptr = g_bias6 + (size_t)head * (NWIN * NWIN);
#pragma unroll
    for (int i = 0; i < 4; i++) {
        int rr = ty * 4 + i;
        int gn = rtile * 64 + rr;
        int labr = lab[gn & 63];
#pragma unroll
        for (int u = 0; u < 20; u++) {
            int m = tx + 16 * u;
            float v = acc[i][u] + bptr[(size_t)gn * NWIN + m];
            if (labr != lab[m & 63]) v -= 100.0f;
            Ss[rr * 321 + m] = v;
        }
    }
    __syncthreads();

    // softmax: one warp per 8 rows
    {
        int lane = tid & 31, wrp = tid >> 5;
        for (int rr = wrp * 8; rr < wrp * 8 + 8; rr++) {
            float* row = Ss + rr * 321;
            float mx = -1e30f;
            for (int m = lane; m < NWIN; m += 32) mx = fmaxf(mx, row[m]);
#pragma unroll
            for (int o = 16; o; o >>= 1) mx = fmaxf(mx, __shfl_xor_sync(0xffffffffu, mx, o));
            float s = 0.f;
            for (int m = lane; m < NWIN; m += 32) {
                float e = __expf(row[m] - mx);
                row[m] = e;
                s += e;
            }
#pragma unroll
            for (int o = 16; o; o >>= 1) s += __shfl_xor_sync(0xffffffffu, s, o);
            float inv = 1.0f / s;
            for (int m = lane; m < NWIN; m += 32) row[m] *= inv;
        }
    }
    __syncthreads();

    // phase 3: out = P @ v (64 x 32)
    float o2[4][2] = {};
    for (int m = 0; m < NWIN; m++) {
        float v0 = vs[m * 33 + tx];
        float v1 = vs[m * 33 + tx + 16];
#pragma unroll
        for (int i = 0; i < 4; i++) {
            float p = Ss[(ty * 4 + i) * 321 + m];
            o2[i][0] += p * v0;
            o2[i][1] += p * v1;
        }
    }
#pragma unroll
    for (int i = 0; i < 4; i++) {
        int gn = rtile * 64 + ty * 4 + i;
        size_t base = ((size_t)b_ * NWIN + gn) * CDIM + head * 32;
        g_a[base + tx]      = o2[i][0];
        g_a[base + tx + 16] = o2[i][1];
    }
}

// ---------------- launch ----------------
extern "C" void kernel_launch(void* const* d_in, const int* in_sizes, int n_in,
                              void* d_out, int out_size) {
    (void)in_sizes; (void)n_in; (void)out_size;
    const float* x      = (const float*)d_in[0];
    const float* ln1_g  = (const float*)d_in[1];
    const float* ln1_b  = (const float*)d_in[2];
    const float* qkv_w  = (const float*)d_in[3];
    const float* qkv_b  = (const float*)d_in[4];
    const float* table  = (const float*)d_in[5];
    const float* proj_w = (const float*)d_in[6];
    const float* proj_b = (const float*)d_in[7];
    const float* ln2_g  = (const float*)d_in[8];
    const float* ln2_b  = (const float*)d_in[9];
    const float* fc1_w  = (const float*)d_in[10];
    const float* fc1_b  = (const float*)d_in[11];
    const float* fc2_w  = (const float*)d_in[12];
    const float* fc2_b  = (const float*)d_in[13];
    float* out = (float*)d_out;

    cudaFuncSetAttribute(attn_kernel, cudaFuncAttributeMaxDynamicSharedMemorySize, ATTN_SMEM);

    // bias table (head, n, m)
    bias_kernel<<<600, 1024>>>(table);
    // LN1 -> g_h
    ln_kernel<0><<<ROWS / 8, 256>>>(x, ln1_g, ln1_b);
    // qkv: gather rows of g_h via winmap, scatter into g_q/g_k/g_v (q pre-scaled)
    gemm64<1, true, EpiQKV><<<dim3(9, ROWS / 64), 256>>>(nullptr, qkv_w, qkv_b, 192, EpiQKV{});
    // attention
    attn_kernel<<<dim3(5, BH), 256, ATTN_SMEM>>>();
    // proj + window-reverse scatter + residual -> g_x1
    gemm64<2, false, EpiProj><<<dim3(3, ROWS / 64), 256>>>(nullptr, proj_w, proj_b, 192, EpiProj{x});
    // LN2 -> g_h
    ln_kernel<1><<<ROWS / 8, 256>>>(nullptr, ln2_g, ln2_b);
    // fc1 + exact gelu -> g_g
    gemm64<1, false, EpiGelu><<<dim3(12, ROWS / 64), 256>>>(nullptr, fc1_w, fc1_b, 192, EpiGelu{});
    // fc2 + residual -> out
    gemm64<3, false, EpiOut><<<dim3(3, ROWS / 64), 256>>>(nullptr, fc2_w, fc2_b, 768, EpiOut{out});
}

// round 4
// speedup vs baseline: 1.1304x; 1.1304x over previous
#include <cuda_runtime.h>
#include <math.h>

// ---------------- problem constants ----------------
#define ROWS      40960
#define CDIM      192
#define NWIN      320
#define BH        768
#define MLPH      768
#define QK_SCALE  0.17677669529663687f

// ---------------- scratch ----------------
__device__ float g_h [ (size_t)ROWS * CDIM ];
__device__ float g_q [ (size_t)BH * NWIN * 32 ];
__device__ float g_k [ (size_t)BH * NWIN * 32 ];
__device__ float g_v [ (size_t)BH * NWIN * 32 ];
__device__ float g_a [ (size_t)ROWS * CDIM ];
__device__ float g_x1[ (size_t)ROWS * CDIM ];
__device__ float g_g [ (size_t)ROWS * MLPH ];
__device__ float g_bias6[ 6 * NWIN * NWIN ];

__device__ __forceinline__ int winmap(int wr) {
    int b_ = wr / NWIN, n = wr - b_ * NWIN;
    int b  = b_ >> 6,  w = b_ & 63;
    int wh = w >> 3,   ww = w & 7;
    int t  = n >> 6;
    int rem = n & 63;
    int i = rem >> 3, j = rem & 7;
    int hs = (wh * 8 + i + 4) & 63;
    int ws = (ww * 8 + j + 4) & 63;
    return ((b * 5 + t) << 12) + (hs << 6) + ws;
}

// ---------------- relative-position bias precompute ----------------
__global__ void bias_kernel(const float* __restrict__ table) {
    int e = blockIdx.x * 1024 + threadIdx.x;
    if (e >= 6 * NWIN * NWIN) return;
    int head = e / (NWIN * NWIN);
    int r = e - head * (NWIN * NWIN);
    int n = r / NWIN, m = r - n * NWIN;
    int t1 = n >> 6, p1 = n & 63, i1 = p1 >> 3, j1 = p1 & 7;
    int t2 = m >> 6, p2 = m & 63, i2 = p2 >> 3, j2 = p2 & 7;
    int idx = (t1 - t2 + 7) * 15 + (i1 - i2 + 7) + (j1 - j2);
    g_bias6[e] = table[idx * 6 + head];
}

// ---------------- LayerNorm ----------------
template<int SRC>
__global__ __launch_bounds__(256) void ln_kernel(const float* __restrict__ in,
                                                 const float* __restrict__ gw,
                                                 const float* __restrict__ bw) {
    int row  = blockIdx.x * 8 + (threadIdx.x >> 5);
    int lane = threadIdx.x & 31;
    const float* src = (SRC == 0) ? in : g_x1;
    const float* p = src + (size_t)row * CDIM;
    float v[6];
    float s = 0.f;
#pragma unroll
    for (int u = 0; u < 6; u++) { v[u] = p[lane + 32 * u]; s += v[u]; }
#pragma unroll
    for (int o = 16; o; o >>= 1) s += __shfl_xor_sync(0xffffffffu, s, o);
    float mu = s * (1.0f / CDIM);
    float q = 0.f;
#pragma unroll
    for (int u = 0; u < 6; u++) { float d = v[u] - mu; q += d * d; }
#pragma unroll
    for (int o = 16; o; o >>= 1) q += __shfl_xor_sync(0xffffffffu, q, o);
    float rs = rsqrtf(q * (1.0f / CDIM) + 1e-5f);
    float* o = g_h + (size_t)row * CDIM;
#pragma unroll
    for (int u = 0; u < 6; u++) {
        int c = lane + 32 * u;
        o[c] = (v[u] - mu) * rs * gw[c] + bw[c];
    }
}

// ---------------- GEMM epilogues ----------------
struct EpiQKV {
    __device__ void operator()(int wr, int oc, float val) const {
        int which = oc / CDIM;
        int rem = oc - which * CDIM;
        int h = rem >> 5, d = rem & 31;
        int b_ = wr / NWIN, n = wr - b_ * NWIN;
        size_t off = ((size_t)(b_ * 6 + h)) * (NWIN * 32) + (size_t)n * 32 + d;
        if (which == 0)      g_q[off] = val * QK_SCALE;
        else if (which == 1) g_k[off] = val;
        else                 g_v[off] = val;
    }
};
struct EpiProj {
    const float* x;
    __device__ void operator()(int wr, int c, float v) const {
        int dst = winmap(wr);
        size_t o = (size_t)dst * CDIM + c;
        g_x1[o] = x[o] + v;
    }
};
struct EpiGelu {
    __device__ void operator()(int r, int c, float v) const {
        g_g[(size_t)r * MLPH + c] = 0.5f * v * (1.0f + erff(v * 0.7071067811865476f));
    }
};
struct EpiOut {
    float* out;
    __device__ void operator()(int r, int c, float v) const {
        size_t o = (size_t)r * CDIM + c;
        out[o] = g_x1[o] + v;
    }
};

// ---------------- 128x64x16 SGEMM, 128 threads, 8x8 microtile, double-buffered ----
template<int ASRC, bool GATHER, class Epi>
__global__ __launch_bounds__(128) void gemm128(const float* __restrict__ Aparam,
                                               const float* __restrict__ W,
                                               const float* __restrict__ bias,
                                               int K, Epi epi) {
    const float* A = (ASRC == 0) ? Aparam : (ASRC == 1) ? g_h : (ASRC == 2) ? g_a : g_g;
    __shared__ float As[2][16 * 132];
    __shared__ float Bs[2][16 * 68];
    int tid = threadIdx.x, bm = blockIdx.y, bn = blockIdx.x;
    int tx = tid & 7, ty = tid >> 3;

    int arow = bm * 128 + tid;
    int asrc = GATHER ? winmap(arow) : arow;
    const float* Ap = A + (size_t)asrc * K;
    int brow = tid >> 1, bkq = (tid & 1) * 8;
    const float* Wp = W + (size_t)(bn * 64 + brow) * K + bkq;

    float4 a0, a1, a2, a3, b0, b1;
    a0 = *(const float4*)(Ap + 0);
    a1 = *(const float4*)(Ap + 4);
    a2 = *(const float4*)(Ap + 8);
    a3 = *(const float4*)(Ap + 12);
    b0 = *(const float4*)(Wp + 0);
    b1 = *(const float4*)(Wp + 4);

    {
        float* as = As[0];
        as[ 0*132+tid]=a0.x; as[ 1*132+tid]=a0.y; as[ 2*132+tid]=a0.z; as[ 3*132+tid]=a0.w;
        as[ 4*132+tid]=a1.x; as[ 5*132+tid]=a1.y; as[ 6*132+tid]=a1.z; as[ 7*132+tid]=a1.w;
        as[ 8*132+tid]=a2.x; as[ 9*132+tid]=a2.y; as[10*132+tid]=a2.z; as[11*132+tid]=a2.w;
        as[12*132+tid]=a3.x; as[13*132+tid]=a3.y; as[14*132+tid]=a3.z; as[15*132+tid]=a3.w;
        float* bs = Bs[0];
        bs[(bkq+0)*68+brow]=b0.x; bs[(bkq+1)*68+brow]=b0.y;
        bs[(bkq+2)*68+brow]=b0.z; bs[(bkq+3)*68+brow]=b0.w;
        bs[(bkq+4)*68+brow]=b1.x; bs[(bkq+5)*68+brow]=b1.y;
        bs[(bkq+6)*68+brow]=b1.z; bs[(bkq+7)*68+brow]=b1.w;
    }
    __syncthreads();

    float acc[8][8] = {};
    int nt = K >> 4;
    for (int t = 0; t < nt; t++) {
        int cur = t & 1;
        if (t + 1 < nt) {
            const float* Ap2 = Ap + (t + 1) * 16;
            const float* Wp2 = Wp + (t + 1) * 16;
            a0 = *(const float4*)(Ap2 + 0);
            a1 = *(const float4*)(Ap2 + 4);
            a2 = *(const float4*)(Ap2 + 8);
            a3 = *(const float4*)(Ap2 + 12);
            b0 = *(const float4*)(Wp2 + 0);
            b1 = *(const float4*)(Wp2 + 4);
        }
        const float* as = As[cur];
        const float* bs = Bs[cur];
#pragma unroll
        for (int kk = 0; kk < 16; kk++) {
            float4 av0 = *(const float4*)&as[kk * 132 + ty * 8];
            float4 av1 = *(const float4*)&as[kk * 132 + ty * 8 + 4];
            float4 bv0 = *(const float4*)&bs[kk * 68 + tx * 8];
            float4 bv1 = *(const float4*)&bs[kk * 68 + tx * 8 + 4];
            float av[8] = {av0.x, av0.y, av0.z, av0.w, av1.x, av1.y, av1.z, av1.w};
            float bv[8] = {bv0.x, bv0.y, bv0.z, bv0.w, bv1.x, bv1.y, bv1.z, bv1.w};
#pragma unroll
            for (int i = 0; i < 8; i++)
#pragma unroll
                for (int j = 0; j < 8; j++) acc[i][j] += av[i] * bv[j];
        }
        if (t + 1 < nt) {
            int nxt = cur ^ 1;
            float* asw = As[nxt];
            asw[ 0*132+tid]=a0.x; asw[ 1*132+tid]=a0.y; asw[ 2*132+tid]=a0.z; asw[ 3*132+tid]=a0.w;
            asw[ 4*132+tid]=a1.x; asw[ 5*132+tid]=a1.y; asw[ 6*132+tid]=a1.z; asw[ 7*132+tid]=a1.w;
            asw[ 8*132+tid]=a2.x; asw[ 9*132+tid]=a2.y; asw[10*132+tid]=a2.z; asw[11*132+tid]=a2.w;
            asw[12*132+tid]=a3.x; asw[13*132+tid]=a3.y; asw[14*132+tid]=a3.z; asw[15*132+tid]=a3.w;
            float* bsw = Bs[nxt];
            bsw[(bkq+0)*68+brow]=b0.x; bsw[(bkq+1)*68+brow]=b0.y;
            bsw[(bkq+2)*68+brow]=b0.z; bsw[(bkq+3)*68+brow]=b0.w;
            bsw[(bkq+4)*68+brow]=b1.x; bsw[(bkq+5)*68+brow]=b1.y;
            bsw[(bkq+6)*68+brow]=b1.z; bsw[(bkq+7)*68+brow]=b1.w;
        }
        __syncthreads();
    }

#pragma unroll
    for (int i = 0; i < 8; i++) {
        int r = bm * 128 + ty * 8 + i;
#pragma unroll
        for (int j = 0; j < 8; j++) {
            int c = bn * 64 + tx * 8 + j;
            epi(r, c, acc[i][j] + bias[c]);
        }
    }
}

// ---------------- flash-style attention ----------------
// grid (5, 768), 256 threads. Streams K/V in 5 chunks of 64 with online softmax.
__global__ __launch_bounds__(256) void attn_kernel() {
    __shared__ float qT[32 * 68];   // [d][r]
    __shared__ float kT[32 * 68];   // [d][m]  (current chunk)
    __shared__ float vT[32 * 68];   // [d][m]
    __shared__ float ps[64 * 68];   // [r][m]
    __shared__ int   lab[64];

    int rtile = blockIdx.x, bh = blockIdx.y;
    int b_ = bh / 6, head = bh - b_ * 6;
    int tid = threadIdx.x;
    int tx = tid & 15, ty = tid >> 4;
    int lr = tid & 63, dg = (tid >> 6) * 8;

    const float* qrow = g_q + ((size_t)bh * NWIN + rtile * 64 + lr) * 32 + dg;
    const float* kp = g_k + (size_t)bh * NWIN * 32 + (size_t)lr * 32 + dg;
    const float* vp = g_v + (size_t)bh * NWIN * 32 + (size_t)lr * 32 + dg;

    {   // q load + transpose
        float4 a = *(const float4*)qrow;
        float4 b = *(const float4*)(qrow + 4);
        qT[(dg+0)*68+lr]=a.x; qT[(dg+1)*68+lr]=a.y; qT[(dg+2)*68+lr]=a.z; qT[(dg+3)*68+lr]=a.w;
        qT[(dg+4)*68+lr]=b.x; qT[(dg+5)*68+lr]=b.y; qT[(dg+6)*68+lr]=b.z; qT[(dg+7)*68+lr]=b.w;
    }
    if (tid < 64) {
        int w = b_ & 63;
        int wh = w >> 3, ww = w & 7;
        int i = tid >> 3, j = tid & 7;
        int hh = wh * 8 + i, wg = ww * 8 + j;
        int lh = hh < 56 ? 0 : (hh < 60 ? 1 : 2);
        int lw = wg < 56 ? 0 : (wg < 60 ? 1 : 2);
        lab[tid] = lh * 3 + lw;
    }
    // prefetch chunk 0
    float4 ka = *(const float4*)kp,     kb = *(const float4*)(kp + 4);
    float4 va = *(const float4*)vp,     vb = *(const float4*)(vp + 4);

    __syncthreads();
    int labm0 = lab[tx*4+0], labm1 = lab[tx*4+1], labm2 = lab[tx*4+2], labm3 = lab[tx*4+3];
    int labr[4];
#pragma unroll
    for (int i = 0; i < 4; i++) labr[i] = lab[ty*4+i];

    float mi[4], li[4], o0[4], o1[4];
#pragma unroll
    for (int i = 0; i < 4; i++) { mi[i] = -1e30f; li[i] = 0.f; o0[i] = 0.f; o1[i] = 0.f; }

    const float* bptr = g_bias6 + (size_t)head * (NWIN * NWIN) + (size_t)(rtile * 64) * NWIN;

    for (int c = 0; c < 5; c++) {
        __syncthreads();   // previous iteration finished reading kT/vT/ps
        kT[(dg+0)*68+lr]=ka.x; kT[(dg+1)*68+lr]=ka.y; kT[(dg+2)*68+lr]=ka.z; kT[(dg+3)*68+lr]=ka.w;
        kT[(dg+4)*68+lr]=kb.x; kT[(dg+5)*68+lr]=kb.y; kT[(dg+6)*68+lr]=kb.z; kT[(dg+7)*68+lr]=kb.w;
        vT[(dg+0)*68+lr]=va.x; vT[(dg+1)*68+lr]=va.y; vT[(dg+2)*68+lr]=va.z; vT[(dg+3)*68+lr]=va.w;
        vT[(dg+4)*68+lr]=vb.x; vT[(dg+5)*68+lr]=vb.y; vT[(dg+6)*68+lr]=vb.z; vT[(dg+7)*68+lr]=vb.w;
        if (c < 4) {
            kp += 64 * 32; vp += 64 * 32;
            ka = *(const float4*)kp; kb = *(const float4*)(kp + 4);
            va = *(const float4*)vp; vb = *(const float4*)(vp + 4);
        }
        __syncthreads();

        // S = q @ k^T (q pre-scaled)
        float acc[4][4] = {};
#pragma unroll
        for (int d = 0; d < 32; d++) {
            float4 qv = *(const float4*)&qT[d * 68 + ty * 4];
            float4 kv = *(const float4*)&kT[d * 68 + tx * 4];
            float qa[4] = {qv.x, qv.y, qv.z, qv.w};
            float kk4[4] = {kv.x, kv.y, kv.z, kv.w};
#pragma unroll
            for (int i = 0; i < 4; i++)
#pragma unroll
                for (int j = 0; j < 4; j++) acc[i][j] += qa[i] * kk4[j];
        }

        // bias + mask + online softmax; write P
#pragma unroll
        for (int i = 0; i < 4; i++) {
            int r = ty * 4 + i;
            float4 b4 = *(const float4*)(bptr + (size_t)r * NWIN + c * 64 + tx * 4);
            int lr_i = labr[i];
            float v0 = acc[i][0] + b4.x + (lr_i != labm0 ? -100.f : 0.f);
            float v1 = acc[i][1] + b4.y + (lr_i != labm1 ? -100.f : 0.f);
            float v2 = acc[i][2] + b4.z + (lr_i != labm2 ? -100.f : 0.f);
            float v3 = acc[i][3] + b4.w + (lr_i != labm3 ? -100.f : 0.f);
            float mloc = fmaxf(fmaxf(v0, v1), fmaxf(v2, v3));
#pragma unroll
            for (int off = 1; off < 16; off <<= 1)
                mloc = fmaxf(mloc, __shfl_xor_sync(0xffffffffu, mloc, off));
            float mnew = fmaxf(mi[i], mloc);
            float p0 = __expf(v0 - mnew), p1 = __expf(v1 - mnew);
            float p2 = __expf(v2 - mnew), p3 = __expf(v3 - mnew);
            float rs = (p0 + p1) + (p2 + p3);
#pragma unroll
            for (int off = 1; off < 16; off <<= 1)
                rs += __shfl_xor_sync(0xffffffffu, rs, off);
            float scale = __expf(mi[i] - mnew);
            li[i] = li[i] * scale + rs;
            o0[i] *= scale; o1[i] *= scale;
            mi[i] = mnew;
            *(float4*)&ps[r * 68 + tx * 4] = make_float4(p0, p1, p2, p3);
        }
        __syncthreads();

        // O += P @ V
#pragma unroll
        for (int m0 = 0; m0 < 64; m0 += 4) {
            float4 va4 = *(const float4*)&vT[tx * 68 + m0];
            float4 vb4 = *(const float4*)&vT[(tx + 16) * 68 + m0];
#pragma unroll
            for (int i = 0; i < 4; i++) {
                float4 p = *(const float4*)&ps[(ty * 4 + i) * 68 + m0];
                o0[i] += p.x * va4.x + p.y * va4.y + p.z * va4.z + p.w * va4.w;
                o1[i] += p.x * vb4.x + p.y * vb4.y + p.z * vb4.z + p.w * vb4.w;
            }
        }
    }

#pragma unroll
    for (int i = 0; i < 4; i++) {
        int gn = rtile * 64 + ty * 4 + i;
        float inv = 1.0f / li[i];
        size_t base = ((size_t)b_ * NWIN + gn) * CDIM + head * 32;
        g_a[base + tx]      = o0[i] * inv;
        g_a[base + tx + 16] = o1[i] * inv;
    }
}

// ---------------- launch ----------------
extern "C" void kernel_launch(void* const* d_in, const int* in_sizes, int n_in,
                              void* d_out, int out_size) {
    (void)in_sizes; (void)n_in; (void)out_size;
    const float* x      = (const float*)d_in[0];
    const float* ln1_g  = (const float*)d_in[1];
    const float* ln1_b  = (const float*)d_in[2];
    const float* qkv_w  = (const float*)d_in[3];
    const float* qkv_b  = (const float*)d_in[4];
    const float* table  = (const float*)d_in[5];
    const float* proj_w = (const float*)d_in[6];
    const float* proj_b = (const float*)d_in[7];
    const float* ln2_g  = (const float*)d_in[8];
    const float* ln2_b  = (const float*)d_in[9];
    const float* fc1_w  = (const float*)d_in[10];
    const float* fc1_b  = (const float*)d_in[11];
    const float* fc2_w  = (const float*)d_in[12];
    const float* fc2_b  = (const float*)d_in[13];
    float* out = (float*)d_out;

    bias_kernel<<<600, 1024>>>(table);
    ln_kernel<0><<<ROWS / 8, 256>>>(x, ln1_g, ln1_b);
    gemm128<1, true,  EpiQKV ><<<dim3(9, 320),  128>>>(nullptr, qkv_w,  qkv_b,  192, EpiQKV{});
    attn_kernel<<<dim3(5, BH), 256>>>();
    gemm128<2, false, EpiProj><<<dim3(3, 320),  128>>>(nullptr, proj_w, proj_b, 192, EpiProj{x});
    ln_kernel<1><<<ROWS / 8, 256>>>(nullptr, ln2_g, ln2_b);
    gemm128<1, false, EpiGelu><<<dim3(12, 320), 128>>>(nullptr, fc1_w,  fc1_b,  192, EpiGelu{});
    gemm128<3, false, EpiOut ><<<dim3(3, 320),  128>>>(nullptr, fc2_w,  fc2_b,  768, EpiOut{out});
}